// round 12
// baseline (speedup 1.0000x reference)
#include <cuda_runtime.h>
#include <math.h>

// MonotonicSpline: y[i] = cubic uniform B-spline(clip(x[i],0,1)).
// coef[0]=c0; coef[j]=c0 + sum_{i<j}(MIN+(MAX-MIN)*sigmoid(raw_delta[i])).
// Uniform knots h=1/40 -> per-segment cubic y=((a*u+b)*u+c)*u+d, u=frac(40x).
//
// PDL two-kernel (R11's overlap: +0.48us vs +2.05us serial) with R2's eval
// interior (8.99us, fastest measured): sequential load->compute->store per
// item, NOT front-batched (front-batching phase-aligns the whole chip into
// read-burst/compute/store-burst and costs ~1us: R4/R9/R11). Only v0/v1 are
// hoisted above gridsync so the prep wait hides real work; v2/v3 issue
// between compute-stores (depth-1 stagger keeps reads+writes co-resident).

static constexpr int   NUM_KNOTS = 40;
static constexpr float MIN_DELTA = 0.5f / NUM_KNOTS;
static constexpr float MAX_DELTA = 3.0f / NUM_KNOTS;
static constexpr int   THREADS   = 256;
static constexpr int   ITEMS     = 4;

__device__ float4 g_poly[NUM_KNOTS];   // per-segment (d,c,b,a)

// ---------------- prep: 1 block, 32 threads (PDL primary) ----------------
__global__ void prep_kernel(const float* __restrict__ c0,
                            const float* __restrict__ raw_delta) {
    __shared__ float coef[NUM_KNOTS + 3];   // 43
    const int lane = threadIdx.x;           // 0..31

    const float scale = MAX_DELTA - MIN_DELTA;
    float d0 = MIN_DELTA + scale / (1.0f + __expf(-raw_delta[lane]));
    float d1 = 0.0f;
    if (lane < 10)
        d1 = MIN_DELTA + scale / (1.0f + __expf(-raw_delta[lane + 32]));
    #pragma unroll
    for (int off = 1; off < 32; off <<= 1) {
        float t0 = __shfl_up_sync(0xffffffffu, d0, off);
        float t1 = __shfl_up_sync(0xffffffffu, d1, off);
        if (lane >= off) { d0 += t0; d1 += t1; }
    }
    float tot0 = __shfl_sync(0xffffffffu, d0, 31);
    float c0v  = __ldg(c0);
    if (lane == 0) coef[0] = c0v;
    coef[lane + 1] = c0v + d0;                        // coef[1..32]
    if (lane < 10) coef[lane + 33] = c0v + tot0 + d1; // coef[33..42]
    __syncwarp();

    #pragma unroll
    for (int j = lane; j < NUM_KNOTS; j += 32) {
        float p0 = coef[j], p1 = coef[j + 1], p2 = coef[j + 2], p3 = coef[j + 3];
        float4 o;
        o.x = (p0 + 4.0f * p1 + p2) * (1.0f / 6.0f);        // u^0
        o.y = (p2 - p0) * 0.5f;                             // u^1
        o.z = (p0 - 2.0f * p1 + p2) * 0.5f;                 // u^2
        o.w = (p3 - p0 + 3.0f * (p1 - p2)) * (1.0f / 6.0f); // u^3
        g_poly[j] = o;
    }
    __threadfence();
    cudaTriggerProgrammaticLaunchCompletion();
}

// ---------------- eval (PDL secondary) ----------------
__device__ __forceinline__ float eval_one(float xv, const float4* __restrict__ rep,
                                          int lane8) {
    float t   = __saturatef(xv) * (float)NUM_KNOTS;   // t in [0,40]
    int   idx = min(__float2int_rz(t), NUM_KNOTS - 1);
    float u   = t - (float)idx;                        // u in [0,1]
    float4 p  = rep[idx * 8 + lane8];                  // conflict-free LDS.128
    return ((p.w * u + p.z) * u + p.y) * u + p.x;
}

__device__ __forceinline__ float4 eval4(float4 v, const float4* __restrict__ rep,
                                        int lane8) {
    float4 o;
    o.x = eval_one(v.x, rep, lane8);
    o.y = eval_one(v.y, rep, lane8);
    o.z = eval_one(v.z, rep, lane8);
    o.w = eval_one(v.w, rep, lane8);
    return o;
}

__global__ void __launch_bounds__(THREADS, 8)
spline_eval_kernel(const float* __restrict__ x,
                   float* __restrict__ y,
                   int n4, int n) {
    __shared__ float4 rep[NUM_KNOTS * 8];   // 8-way replicated table, 5 KB

    const int tid  = threadIdx.x;
    const int base = blockIdx.x * (THREADS * ITEMS) + tid;
    const bool full = (blockIdx.x + 1) * (THREADS * ITEMS) <= n4;
    const float4* __restrict__ x4 = reinterpret_cast<const float4*>(x);
    float4* __restrict__ y4 = reinterpret_cast<float4*>(y);

    // ---- hoist only items 0,1: real work under the prep wait, MLP_p1=2 ----
    float4 v0, v1;
    if (full) {
        v0 = x4[base + 0 * THREADS];
        v1 = x4[base + 1 * THREADS];
    } else {
        if (base + 0 * THREADS < n4) v0 = x4[base + 0 * THREADS];
        if (base + 1 * THREADS < n4) v1 = x4[base + 1 * THREADS];
    }

    // ---- wait for prep, then cheap table copy (640B from gmem) ----
    cudaGridDependencySynchronize();
    #pragma unroll
    for (int e = tid; e < NUM_KNOTS * 8; e += THREADS)
        rep[e] = g_poly[e >> 3];
    __syncthreads();

    // ---- staggered load/compute/store (R2 interior + depth-1 stagger) ----
    const int lane8 = tid & 7;
    if (full) {
        float4 v2 = x4[base + 2 * THREADS];            // issue before compute0
        y4[base + 0 * THREADS] = eval4(v0, rep, lane8);
        float4 v3 = x4[base + 3 * THREADS];            // issue before compute1
        y4[base + 1 * THREADS] = eval4(v1, rep, lane8);
        y4[base + 2 * THREADS] = eval4(v2, rep, lane8);
        y4[base + 3 * THREADS] = eval4(v3, rep, lane8);
    } else {
        if (base + 0 * THREADS < n4) y4[base + 0 * THREADS] = eval4(v0, rep, lane8);
        if (base + 1 * THREADS < n4) y4[base + 1 * THREADS] = eval4(v1, rep, lane8);
        if (base + 2 * THREADS < n4) {
            float4 v2 = x4[base + 2 * THREADS];
            y4[base + 2 * THREADS] = eval4(v2, rep, lane8);
        }
        if (base + 3 * THREADS < n4) {
            float4 v3 = x4[base + 3 * THREADS];
            y4[base + 3 * THREADS] = eval4(v3, rep, lane8);
        }
    }

    // scalar tail (n % 4 != 0) — block 0 only
    if (blockIdx.x == 0) {
        int j = n4 * 4 + tid;
        if (j < n) y[j] = eval_one(x[j], rep, lane8);
    }
}

extern "C" void kernel_launch(void* const* d_in, const int* in_sizes, int n_in,
                              void* d_out, int out_size) {
    const float* x         = (const float*)d_in[0];
    // d_in[1] = grid (uniform; values implied by construction)
    const float* c0        = (const float*)d_in[2];
    const float* raw_delta = (const float*)d_in[3];
    float* y = (float*)d_out;

    int n  = in_sizes[0];
    int n4 = n / 4;

    int per_block = THREADS * ITEMS;
    int blocks = (n4 + per_block - 1) / per_block;
    if (blocks == 0) blocks = 1;

    // primary: tiny prep
    prep_kernel<<<1, 32>>>(c0, raw_delta);

    // secondary: eval with programmatic stream serialization (PDL overlap)
    cudaLaunchConfig_t cfg = {};
    cfg.gridDim  = dim3((unsigned)blocks, 1, 1);
    cfg.blockDim = dim3(THREADS, 1, 1);
    cfg.dynamicSmemBytes = 0;
    cfg.stream = 0;
    cudaLaunchAttribute attrs[1];
    attrs[0].id = cudaLaunchAttributeProgrammaticStreamSerialization;
    attrs[0].val.programmaticStreamSerializationAllowed = 1;
    cfg.attrs = attrs;
    cfg.numAttrs = 1;
    cudaLaunchKernelEx(&cfg, spline_eval_kernel, x, y, n4, n);
}

// round 13
// speedup vs baseline: 1.0313x; 1.0313x over previous
#include <cuda_runtime.h>
#include <math.h>

// MonotonicSpline: y[i] = cubic uniform B-spline(clip(x[i],0,1)).
// coef[0]=c0; coef[j]=c0 + sum_{i<j}(MIN+(MAX-MIN)*sigmoid(raw_delta[i])).
// Uniform knots h=1/40 -> per-segment cubic y=((a*u+b)*u+c)*u+d, u=frac(40x).
//
// Consolidation of best-measured pieces (12 rounds of evidence):
//  - SINGLE fused node (two-node/PDL variants pay +0.3..2us: R2/R11/R12)
//  - staggered interior (9.66us eval: R5/R12), NOT front-batched (10.0: R9)
//  - warp0's raw_delta/c0 LDGs issued first -> shortest barrier convoy
//  - ALIGNED template: zero bounds checks when n4 divides the grid exactly
//  - fused clamp (one fmin+fmax, no idx clamp), rep+lane8 precomputed
//  - 8-way bank-replicated smem table (guaranteed conflict-free LDS.128)
//  - launch_bounds(256,8): regs<=32, 1024 blocks = one resident wave

static constexpr int   NUM_KNOTS = 40;
static constexpr float MIN_DELTA = 0.5f / NUM_KNOTS;
static constexpr float MAX_DELTA = 3.0f / NUM_KNOTS;
static constexpr int   THREADS   = 256;
static constexpr int   ITEMS     = 4;

__device__ __forceinline__ float eval_one(float xv, const float4* __restrict__ repl) {
    // one fused clamp: t in [0, 39.999985]; u=t-idx in [0,1) continuous at x=1
    float t   = fminf(fmaxf(xv, 0.0f) * (float)NUM_KNOTS, 39.999985f);
    int   idx = __float2int_rz(t);
    float u   = t - (float)idx;
    float4 p  = repl[idx * 8];              // repl = rep + lane8 (conflict-free)
    return ((p.w * u + p.z) * u + p.y) * u + p.x;
}

__device__ __forceinline__ float4 eval4(float4 v, const float4* __restrict__ repl) {
    float4 o;
    o.x = eval_one(v.x, repl);
    o.y = eval_one(v.y, repl);
    o.z = eval_one(v.z, repl);
    o.w = eval_one(v.w, repl);
    return o;
}

template <bool ALIGNED>
__global__ void __launch_bounds__(THREADS, 8)
spline_fused_kernel(const float* __restrict__ x,
                    const float* __restrict__ c0,
                    const float* __restrict__ raw_delta,
                    float* __restrict__ y,
                    int n4, int n) {
    __shared__ float  coef[NUM_KNOTS + 3];      // 43
    __shared__ float4 rep[NUM_KNOTS * 8];       // 8-way replicated table, 5 KB

    const int tid  = threadIdx.x;
    const int lane = tid & 31;
    const int base = blockIdx.x * (THREADS * ITEMS) + tid;
    const float4* __restrict__ x4 = reinterpret_cast<const float4*>(x);
    float4* __restrict__ y4 = reinterpret_cast<float4*>(y);

    // ---- warp 0: issue prologue input loads BEFORE anything else ----
    float rd0 = 0.0f, rd1 = 0.0f, c0v = 0.0f;
    if (tid < 32) {
        rd0 = raw_delta[lane];
        if (lane < 10) rd1 = raw_delta[lane + 32];
        c0v = __ldg(c0);
    }

    // ---- hoist items 0,1 (fill the barrier-wait shadow; MLP_p1=2) ----
    float4 v0, v1;
    if (ALIGNED) {
        v0 = x4[base + 0 * THREADS];
        v1 = x4[base + 1 * THREADS];
    } else {
        if (base + 0 * THREADS < n4) v0 = x4[base + 0 * THREADS];
        if (base + 1 * THREADS < n4) v1 = x4[base + 1 * THREADS];
    }

    // ---- warp 0: sigmoid -> shfl scan -> coef -> replicated poly table ----
    if (tid < 32) {
        const float scale = MAX_DELTA - MIN_DELTA;
        float d0 = MIN_DELTA + scale / (1.0f + __expf(-rd0));
        float d1 = MIN_DELTA + scale / (1.0f + __expf(-rd1));
        #pragma unroll
        for (int off = 1; off < 32; off <<= 1) {
            float t0 = __shfl_up_sync(0xffffffffu, d0, off);
            float t1 = __shfl_up_sync(0xffffffffu, d1, off);
            if (lane >= off) { d0 += t0; d1 += t1; }
        }
        float tot0 = __shfl_sync(0xffffffffu, d0, 31);
        if (lane == 0) coef[0] = c0v;
        coef[lane + 1] = c0v + d0;                        // coef[1..32]
        if (lane < 10) coef[lane + 33] = c0v + tot0 + d1; // coef[33..42]
        __syncwarp();
        #pragma unroll
        for (int e = lane; e < NUM_KNOTS * 8; e += 32) {  // conflict-free STS.128
            int j = e >> 3;
            float p0 = coef[j], p1 = coef[j + 1], p2 = coef[j + 2], p3 = coef[j + 3];
            float4 o;
            o.x = (p0 + 4.0f * p1 + p2) * (1.0f / 6.0f);        // u^0
            o.y = (p2 - p0) * 0.5f;                             // u^1
            o.z = (p0 - 2.0f * p1 + p2) * 0.5f;                 // u^2
            o.w = (p3 - p0 + 3.0f * (p1 - p2)) * (1.0f / 6.0f); // u^3
            rep[e] = o;
        }
    }
    __syncthreads();

    // ---- staggered load/compute/store ----
    const float4* __restrict__ repl = rep + (tid & 7);
    if (ALIGNED) {
        float4 v2 = x4[base + 2 * THREADS];            // issue before compute0
        y4[base + 0 * THREADS] = eval4(v0, repl);
        float4 v3 = x4[base + 3 * THREADS];            // issue before compute1
        y4[base + 1 * THREADS] = eval4(v1, repl);
        y4[base + 2 * THREADS] = eval4(v2, repl);
        y4[base + 3 * THREADS] = eval4(v3, repl);
    } else {
        if (base + 0 * THREADS < n4) y4[base + 0 * THREADS] = eval4(v0, repl);
        if (base + 1 * THREADS < n4) y4[base + 1 * THREADS] = eval4(v1, repl);
        if (base + 2 * THREADS < n4) {
            float4 v2 = x4[base + 2 * THREADS];
            y4[base + 2 * THREADS] = eval4(v2, repl);
        }
        if (base + 3 * THREADS < n4) {
            float4 v3 = x4[base + 3 * THREADS];
            y4[base + 3 * THREADS] = eval4(v3, repl);
        }
        // scalar tail (n % 4 != 0) — block 0 only, only in unaligned variant
        if (blockIdx.x == 0) {
            int j = n4 * 4 + tid;
            if (j < n) y[j] = eval_one(x[j], repl);
        }
    }
}

extern "C" void kernel_launch(void* const* d_in, const int* in_sizes, int n_in,
                              void* d_out, int out_size) {
    const float* x         = (const float*)d_in[0];
    // d_in[1] = grid (uniform; values implied by construction)
    const float* c0        = (const float*)d_in[2];
    const float* raw_delta = (const float*)d_in[3];
    float* y = (float*)d_out;

    int n  = in_sizes[0];
    int n4 = n / 4;

    int per_block = THREADS * ITEMS;
    int blocks = (n4 + per_block - 1) / per_block;
    if (blocks == 0) blocks = 1;

    bool aligned = (n % 4 == 0) && (n4 % per_block == 0);
    if (aligned)
        spline_fused_kernel<true><<<blocks, THREADS>>>(x, c0, raw_delta, y, n4, n);
    else
        spline_fused_kernel<false><<<blocks, THREADS>>>(x, c0, raw_delta, y, n4, n);
}